// round 13
// baseline (speedup 1.0000x reference)
#include <cuda_runtime.h>
#include <math.h>

#define BATCH 8
#define NPROP 1000
#define NCLS  80
#define NLOG  81
#define DFEAT 2048
#define KCAND 1024
#define NFLAT (NPROP*NCLS)   /* 80000 */
#define NTH   10
#define SCORE_T 1e-4f
#define CBUF   4096
#define BPI    16            /* front blocks per image */
#define NBLK1  (BATCH*BPI)   /* 128 */
#define HBINS  512           /* probs <= 1.0 -> key>>21 <= 508 */

typedef unsigned long long u64;

/* ---------------- scratch (static device globals; no allocation) -------- */
__device__ int      g_hist[BATCH][HBINS];  /* zeroed by k_mid for next replay */
__device__ int      g_ccount[BATCH];
__device__ u64      g_cbuf[BATCH][CBUF];
__device__ float    g_boxv[BATCH][KCAND][4];
__device__ int      g_prop[BATCH][KCAND];
__device__ short    g_member[BATCH][KCAND];
__device__ int      g_cnt[BATCH][NCLS];
__device__ int      g_cstart[BATCH][NCLS + 1];
__device__ unsigned g_validw[BATCH][32];
__device__ unsigned g_keepw[BATCH][NTH][32];   /* zeroed by k_mid */
__device__ unsigned char g_cmat_ovf[BATCH][1 << 20];

/* ------- device-wide sense barrier (128 blocks, all wave-1 resident) ----- */
__device__ unsigned g_ctr = 0;
__device__ unsigned g_gen = 0;
__device__ __forceinline__ void gridbar(unsigned nb)
{
    __syncthreads();
    if (threadIdx.x == 0) {
        __threadfence();
        unsigned gen = atomicAdd(&g_gen, 0u);
        if (atomicAdd(&g_ctr, 1u) == nb - 1u) {
            g_ctr = 0;
            __threadfence();
            atomicExch(&g_gen, gen + 1u);
        } else {
            while (atomicAdd(&g_gen, 0u) == gen) { __nanosleep(64); }
        }
        __threadfence();
    }
    __syncthreads();
}

/* ------ kernel 1: softmax -> keys(shared) + hist -> barrier -> compact --- */
__global__ void __launch_bounds__(256) k_front(const float* __restrict__ logits)
{
    int blk = blockIdx.x;
    int b  = blk / BPI;
    int sb = blk % BPI;
    int r0   = sb * 62 + (sb < 8 ? sb : 8);
    int rows = 62 + (sb < 8 ? 1 : 0);
    int nel  = rows * NCLS;

    __shared__ unsigned sh_keys[63 * NCLS];  /* 5040 */
    __shared__ int sh_hist[HBINS];
    __shared__ int sh_d1;

    int tid = threadIdx.x, lane = tid & 31, wid = tid >> 5;

    for (int i = tid; i < HBINS; i += 256) sh_hist[i] = 0;
    __syncthreads();

    for (int r = wid; r < rows; r += 8) {
        const float* p = logits + (size_t)(b * NPROP + r0 + r) * NLOG;
        float v0 = p[lane];
        float v1 = p[lane + 32];
        float v2 = (lane + 64 < NLOG) ? p[lane + 64] : -INFINITY;
        float m = fmaxf(fmaxf(v0, v1), v2);
        #pragma unroll
        for (int o = 16; o; o >>= 1) m = fmaxf(m, __shfl_xor_sync(0xffffffffu, m, o));
        float e0 = expf(v0 - m);
        float e1 = expf(v1 - m);
        float e2 = (lane + 64 < NLOG) ? expf(v2 - m) : 0.0f;
        float s = e0 + e1 + e2;
        #pragma unroll
        for (int o = 16; o; o >>= 1) s += __shfl_xor_sync(0xffffffffu, s, o);
        float p0 = e0 / s, p1 = e1 / s, p2 = e2 / s;
        unsigned k0 = (p0 > SCORE_T) ? __float_as_uint(p0) : 0u;
        unsigned k1 = (p1 > SCORE_T) ? __float_as_uint(p1) : 0u;
        unsigned k2 = (p2 > SCORE_T) ? __float_as_uint(p2) : 0u;
        sh_keys[r * NCLS + lane]      = k0;
        sh_keys[r * NCLS + lane + 32] = k1;
        if (k0) atomicAdd(&sh_hist[min(k0 >> 21, (unsigned)(HBINS - 1))], 1);
        if (k1) atomicAdd(&sh_hist[min(k1 >> 21, (unsigned)(HBINS - 1))], 1);
        if (lane + 64 < NCLS) {
            sh_keys[r * NCLS + lane + 64] = k2;
            if (k2) atomicAdd(&sh_hist[min(k2 >> 21, (unsigned)(HBINS - 1))], 1);
        }
    }
    __syncthreads();

    for (int i = tid; i < HBINS; i += 256) {
        int v = sh_hist[i];
        if (v) atomicAdd(&g_hist[b][i], v);
    }

    gridbar(NBLK1);

    /* pivot: highest bin where cumulative (from top) reaches KCAND */
    if (wid == 0) {
        int run = 0, found = 0;
        for (int g = 0; g < HBINS / 32; ++g) {
            int bin = HBINS - 1 - (g * 32 + lane);
            int c = g_hist[b][bin];
            int inc = c;
            #pragma unroll
            for (int o = 1; o < 32; o <<= 1) {
                int u = __shfl_up_sync(0xffffffffu, inc, o);
                if (lane >= o) inc += u;
            }
            int cum = run + inc;
            unsigned bal = __ballot_sync(0xffffffffu, cum >= KCAND);
            if (bal) {
                int fl = __ffs(bal) - 1;
                if (lane == fl) sh_d1 = bin;
                found = 1;
            }
            run += __shfl_sync(0xffffffffu, inc, 31);
            if (found) break;
        }
        if (!found && lane == 0) sh_d1 = 0;
    }
    __syncthreads();
    unsigned d1 = (unsigned)sh_d1;

    int iters = (nel + 255) / 256;
    for (int k = 0; k < iters; ++k) {
        int i = tid + k * 256;
        bool in = (i < nel);
        unsigned key = in ? sh_keys[i] : 0u;
        bool q = in && key && (min(key >> 21, (unsigned)(HBINS - 1)) >= d1);
        unsigned bal = __ballot_sync(0xffffffffu, q);
        if (bal) {
            int ldr = __ffs(bal) - 1;
            int pos = 0;
            if (lane == ldr) pos = atomicAdd(&g_ccount[b], __popc(bal));
            pos = __shfl_sync(0xffffffffu, pos, ldr);
            if (q) {
                int my = pos + __popc(bal & ((1u << lane) - 1));
                if (my < CBUF) {
                    unsigned idx = (unsigned)(r0 * NCLS + i);
                    g_cbuf[b][my] = ((u64)(key ^ 0xFFFFFFFFu) << 32) | idx;
                }
            }
        }
    }
}

/* ------ kernel 2: refine pivot + sort + finalize + class lists ----------- */
__global__ void __launch_bounds__(1024) k_mid(const float* __restrict__ boxes,
                                              const int*   __restrict__ hw)
{
    int b = blockIdx.x;
    int tid = threadIdx.x, lane = tid & 31, wid = tid >> 5;

    __shared__ u64 sA[CBUF];                 /* 32KB sort buffer */
    __shared__ int sh_hist2[2048];           /* 8KB refinement histogram */
    __shared__ unsigned short h2[NCLS][32];
    __shared__ int sh_cnt[NCLS];
    __shared__ int sh_cstart[NCLS + 1];
    __shared__ int s_cnt, sh_d1min, sh_G, sh_d2, sh_cnt2;

    if (tid == 0) {
        s_cnt = g_ccount[b];
        sh_d1min = 0x7FFFFFFF;
        sh_G = 0;
        sh_cnt2 = 0;
        g_ccount[b] = 0;                     /* replay reset */
    }
    for (int i = tid; i < 2048; i += 1024) sh_hist2[i] = 0;
    if (tid < HBINS) g_hist[b][tid] = 0;     /* replay reset */
    if (tid < NTH * 32) ((unsigned*)g_keepw[b])[tid] = 0;
    __syncthreads();
    int cnt = s_cnt;
    if (cnt > CBUF) cnt = CBUF;

    /* ---- pivot refinement: narrow candidates to ~KCAND before sorting ---- */
    /* pass A: d1 = min(hi11) over candidates (equals front's pivot bin) */
    {
        int lmin = 0x7FFFFFFF;
        for (int i = tid; i < cnt; i += 1024) {
            unsigned key = (unsigned)(g_cbuf[b][i] >> 32) ^ 0xFFFFFFFFu;
            int hi = (int)(key >> 21);
            if (hi < lmin) lmin = hi;
        }
        #pragma unroll
        for (int o = 16; o; o >>= 1) lmin = min(lmin, __shfl_xor_sync(0xffffffffu, lmin, o));
        if (lane == 0 && lmin != 0x7FFFFFFF) atomicMin(&sh_d1min, lmin);
    }
    __syncthreads();
    int d1m = sh_d1min;

    /* pass B: count hi11>d1 (G) and histogram bits[10:21) of pivot-bin keys */
    {
        int lg = 0;
        for (int i = tid; i < cnt; i += 1024) {
            unsigned key = (unsigned)(g_cbuf[b][i] >> 32) ^ 0xFFFFFFFFu;
            int hi = (int)(key >> 21);
            if (hi > d1m) lg++;
            else atomicAdd(&sh_hist2[(key >> 10) & 0x7FF], 1);
        }
        #pragma unroll
        for (int o = 16; o; o >>= 1) lg += __shfl_xor_sync(0xffffffffu, lg, o);
        if (lane == 0 && lg) atomicAdd(&sh_G, lg);
    }
    __syncthreads();

    /* scan: highest d2 with G + cum(bins >= d2) >= KCAND */
    if (wid == 0) {
        int need = KCAND - sh_G;
        if (need <= 0) need = 1;
        int run = 0, found = 0;
        for (int g = 0; g < 64; ++g) {
            int bin = 2047 - (g * 32 + lane);
            int c = sh_hist2[bin];
            int inc = c;
            #pragma unroll
            for (int o = 1; o < 32; o <<= 1) {
                int u = __shfl_up_sync(0xffffffffu, inc, o);
                if (lane >= o) inc += u;
            }
            int cum = run + inc;
            unsigned bal = __ballot_sync(0xffffffffu, cum >= need);
            if (bal) {
                int fl = __ffs(bal) - 1;
                if (lane == fl) sh_d2 = bin;
                found = 1;
            }
            run += __shfl_sync(0xffffffffu, inc, 31);
            if (found) break;
        }
        if (!found && lane == 0) sh_d2 = 0;
    }
    __syncthreads();
    unsigned piv22 = (cnt <= KCAND) ? 0u
                    : (((unsigned)d1m << 11) | (unsigned)sh_d2);

    /* pass C: compact qualifying candidates into sA */
    for (int i = tid; i < cnt; i += 1024) {
        u64 v = g_cbuf[b][i];
        unsigned key = (unsigned)(v >> 32) ^ 0xFFFFFFFFu;
        if ((key >> 10) >= piv22) {
            int pos = atomicAdd(&sh_cnt2, 1);
            if (pos < CBUF) sA[pos] = v;
        }
    }
    __syncthreads();
    int cnt2 = sh_cnt2;
    if (cnt2 > CBUF) cnt2 = CBUF;
    int M = 1024;
    while (M < cnt2) M <<= 1;
    int E = M >> 10;
    for (int i = tid; i < M; i += 1024)
        if (i >= cnt2) sA[i] = 0xFFFFFFFFFFFFFFFFULL;
    __syncthreads();

    /* hybrid bitonic sort ascending on (~val, idx); sub-sequences first */
    for (int k2 = 2; k2 < M; k2 <<= 1) {
        for (int j = k2 >> 1; j >= 32; j >>= 1) {
            for (int e = 0; e < E; ++e) {
                int i = tid + (e << 10);
                int ixj = i ^ j;
                if (ixj > i) {
                    u64 a = sA[i], c = sA[ixj];
                    bool up = ((i & k2) == 0);
                    if ((a > c) == up) { sA[i] = c; sA[ixj] = a; }
                }
            }
            __syncthreads();
        }
        int j0 = ((k2 >> 1) < 16) ? (k2 >> 1) : 16;
        for (int e = 0; e < E; ++e) {
            int i = tid + (e << 10);
            u64 a = sA[i];
            bool up = ((i & k2) == 0);
            #pragma unroll
            for (int j = 16; j > 0; j >>= 1) {
                if (j <= j0) {
                    u64 c = __shfl_xor_sync(0xffffffffu, a, j);
                    bool keepmin = (((i & j) == 0) == up);
                    bool amin = (a < c);
                    a = (keepmin == amin) ? a : c;
                }
            }
            sA[i] = a;
        }
        __syncthreads();
    }
    /* final merge k2 = M ascending; only lowest KCAND matter */
    {
        for (int j = M >> 1; j >= 32; j >>= 1) {
            int lim = (2 * j > KCAND) ? 2 * j : KCAND;
            int El = lim >> 10;
            for (int e = 0; e < El; ++e) {
                int i = tid + (e << 10);
                int ixj = i ^ j;
                if (ixj > i) {
                    u64 a = sA[i], c = sA[ixj];
                    if (a > c) { sA[i] = c; sA[ixj] = a; }
                }
            }
            __syncthreads();
        }
        int i = tid;
        u64 a = sA[i];
        #pragma unroll
        for (int j = 16; j > 0; j >>= 1) {
            u64 c = __shfl_xor_sync(0xffffffffu, a, j);
            bool keepmin = ((i & j) == 0);
            bool amin = (a < c);
            a = (keepmin == amin) ? a : c;
        }
        sA[i] = a;
        __syncthreads();
    }

    u64 v = sA[tid];
    unsigned key = (unsigned)(v >> 32) ^ 0xFFFFFFFFu;
    unsigned idxu = (unsigned)(v & 0xFFFFFFFFu);
    int idx = (idxu < NFLAT) ? (int)idxu : 0;
    int cls  = idx % NCLS;
    int prop = idx / NCLS;

    float h = (float)hw[b * 2 + 0];
    float w = (float)hw[b * 2 + 1];
    const float* bp = boxes + ((size_t)(b * NPROP + prop) * NCLS + cls) * 4;
    float x1 = fminf(fmaxf(bp[0], 0.0f), w);
    float y1 = fminf(fmaxf(bp[1], 0.0f), h);
    float x2 = fminf(fmaxf(bp[2], 0.0f), w);
    float y2 = fminf(fmaxf(bp[3], 0.0f), h);
    float off = (float)cls * 4096.0f;
    x1 += off; y1 += off; x2 += off; y2 += off;

    g_boxv[b][tid][0] = x1; g_boxv[b][tid][1] = y1;
    g_boxv[b][tid][2] = x2; g_boxv[b][tid][3] = y2;
    g_prop[b][tid] = prop;

    unsigned vb = __ballot_sync(0xffffffffu, key != 0u);
    if (lane == 0) g_validw[b][wid] = vb;

    /* per-class member lists (stable in candidate order) */
    for (int i = tid; i < NCLS * 32; i += 1024) ((unsigned short*)h2)[i] = 0;
    __syncthreads();

    unsigned pm = __match_any_sync(0xffffffffu, cls);
    int leader = __ffs(pm) - 1;
    int intra  = __popc(pm & ((1u << lane) - 1));
    if (lane == leader) h2[cls][wid] = (unsigned short)__popc(pm);
    __syncthreads();

    if (tid < NCLS) {
        int acc = 0;
        #pragma unroll
        for (int w2 = 0; w2 < 32; ++w2) {
            int t = h2[tid][w2];
            h2[tid][w2] = (unsigned short)acc;
            acc += t;
        }
        sh_cnt[tid] = acc;
    }
    __syncthreads();
    if (tid == 0) {
        int acc = 0;
        for (int c = 0; c < NCLS; ++c) {
            sh_cstart[c] = acc;
            acc += sh_cnt[c];
        }
        sh_cstart[NCLS] = acc;
    }
    __syncthreads();

    int posc = sh_cstart[cls] + (int)h2[cls][wid] + intra;
    g_member[b][posc] = (short)tid;
    if (tid < NCLS) g_cnt[b][tid] = sh_cnt[tid];
    if (tid <= NCLS) g_cstart[b][tid] = sh_cstart[tid];
}

/* ------ kernel 3: per-class IOU + 10-threshold greedy chains ------------- */
__global__ void __launch_bounds__(128) k_nms2()
{
    int c = blockIdx.x;
    int b = blockIdx.y;
    int tid = threadIdx.x;

    int n = g_cnt[b][c];
    if (n == 0) return;
    int start = g_cstart[b][c];

    __shared__ short mem[KCAND];
    __shared__ float4 bx[256];               /* staged boxes if n<=256 */
    __shared__ unsigned char cm[128 * 128];
    __shared__ u64 sup_sh[NTH][16];
    __shared__ unsigned valid_sh[32];

    if (tid < 32) valid_sh[tid] = g_validw[b][tid];
    for (int i = tid; i < n; i += 128) mem[i] = g_member[b][start + i];
    __syncthreads();
    bool stage_bx = (n <= 256);
    if (stage_bx) {
        for (int i = tid; i < n; i += 128)
            bx[i] = ((const float4*)g_boxv[b])[(int)mem[i]];
    }
    bool use_sh = (n <= 128);
    unsigned char* Mp = use_sh ? cm : &g_cmat_ovf[b][start * 1024];
    __syncthreads();

    /* IOU -> per-pair threshold-count bytes */
    const float4* gb = (const float4*)g_boxv[b];
    int tot = n * n;
    for (int p = tid; p < tot; p += 128) {
        int q = p / n;
        int r = p - q * n;
        float4 bq = stage_bx ? bx[q] : gb[(int)mem[q]];
        float4 br = stage_bx ? bx[r] : gb[(int)mem[r]];
        float iw = fminf(bq.z, br.z) - fmaxf(bq.x, br.x);
        float ih = fminf(bq.w, br.w) - fmaxf(bq.y, br.y);
        iw = fmaxf(iw, 0.0f);
        ih = fmaxf(ih, 0.0f);
        float inter = iw * ih;
        float aq = (bq.z - bq.x) * (bq.w - bq.y);
        float ar = (br.z - br.x) * (br.w - br.y);
        float uni = aq + ar - inter;
        float iou = (uni > 0.0f) ? (inter / uni) : 0.0f;
        int cc = 0;
        cc += (iou > 0.001f); cc += (iou > 0.101f); cc += (iou > 0.201f);
        cc += (iou > 0.301f); cc += (iou > 0.401f); cc += (iou > 0.501f);
        cc += (iou > 0.601f); cc += (iou > 0.701f); cc += (iou > 0.801f);
        cc += (iou > 0.901f);
        Mp[p] = (unsigned char)cc;
    }
    if (tid < NTH * 16) ((u64*)sup_sh)[tid] = 0;
    __syncthreads();

    /* 10 serial greedy chains, one per thread */
    if (tid < NTH) {
        int t = tid;
        for (int r = 0; r < n; ++r) {
            if ((sup_sh[t][r >> 6] >> (r & 63)) & 1ULL) continue;
            int gi = (int)mem[r];
            if (!((valid_sh[gi >> 5] >> (gi & 31)) & 1u)) continue;
            atomicOr(&g_keepw[b][t][gi >> 5], 1u << (gi & 31));
            const unsigned char* row = Mp + r * n;
            u64 acc[16];
            int hi = (n + 63) >> 6;
            #pragma unroll 4
            for (int w2 = 0; w2 < hi; ++w2) acc[w2] = sup_sh[t][w2];
            for (int rr = r + 1; rr < n; ++rr)
                if ((int)row[rr] > t) acc[rr >> 6] |= 1ULL << (rr & 63);
            #pragma unroll 4
            for (int w2 = 0; w2 < hi; ++w2) sup_sh[t][w2] = acc[w2];
        }
    }
}

/* ------ kernel 4: threshold select + top-6 + transposed feature gather --- */
__global__ void __launch_bounds__(256) k_pick(const float* __restrict__ feats,
                                              float* __restrict__ out)
{
    int b = blockIdx.x;
    int s = blockIdx.y;          /* d-slice [s*512, (s+1)*512) */
    int tid = threadIdx.x;

    __shared__ unsigned keepw[NTH][32];
    __shared__ int cnt_t[NTH];
    __shared__ int selp[6];
    __shared__ __align__(16) float sh[512 * 6];   /* 12KB transpose buffer */

    if (tid < NTH * 32) ((unsigned*)keepw)[tid] = ((const unsigned*)g_keepw[b])[tid];
    __syncthreads();

    if (tid < NTH) {
        int ssum = 0;
        #pragma unroll
        for (int w2 = 0; w2 < 32; ++w2) ssum += __popc(keepw[tid][w2]);
        cnt_t[tid] = ssum;
    }
    __syncthreads();

    if (tid == 0) {
        int tsel = NTH - 1;
        for (int q = 0; q < NTH; ++q)
            if (cnt_t[q] >= 6) { tsel = q; break; }
        int found = 0;
        for (int w2 = 0; w2 < 32 && found < 6; ++w2) {
            unsigned m = keepw[tsel][w2];
            while (m && found < 6) {
                int bpos = __ffs(m) - 1;
                m &= m - 1;
                selp[found++] = g_prop[b][w2 * 32 + bpos];
            }
        }
        if (found < 6) {
            for (int gi = 0; gi < KCAND && found < 6; ++gi)
                if (!((keepw[tsel][gi >> 5] >> (gi & 31)) & 1u))
                    selp[found++] = g_prop[b][gi];
        }
    }
    __syncthreads();

    const float* fb = feats + (size_t)b * NPROP * DFEAT;
    int d0 = s * 512;
    #pragma unroll
    for (int j = 0; j < 6; ++j) {
        const float* src = fb + (size_t)selp[j] * DFEAT + d0;
        for (int d = tid; d < 512; d += 256)
            sh[d * 6 + j] = src[d];
    }
    __syncthreads();

    float4* ov = (float4*)(out + (size_t)b * DFEAT * 6 + (size_t)d0 * 6);
    const float4* sv = (const float4*)sh;
    for (int i = tid; i < 768; i += 256) ov[i] = sv[i];
}

/* ---------------- launch -------------------------------------------------- */
extern "C" void kernel_launch(void* const* d_in, const int* in_sizes, int n_in,
                              void* d_out, int out_size)
{
    (void)in_sizes; (void)n_in; (void)out_size;
    const float* logits = (const float*)d_in[0];
    const float* boxes  = (const float*)d_in[1];
    const float* feats  = (const float*)d_in[2];
    const int*   hw     = (const int*)  d_in[3];
    float* out = (float*)d_out;

    k_front<<<NBLK1, 256>>>(logits);
    k_mid<<<BATCH, 1024>>>(boxes, hw);
    k_nms2<<<dim3(NCLS, BATCH), 128>>>();
    k_pick<<<dim3(BATCH, 4), 256>>>(feats, out);
}

// round 14
// speedup vs baseline: 1.1703x; 1.1703x over previous
#include <cuda_runtime.h>
#include <math.h>

#define BATCH 8
#define NPROP 1000
#define NCLS  80
#define NLOG  81
#define DFEAT 2048
#define KCAND 1024
#define NFLAT (NPROP*NCLS)   /* 80000 */
#define NTH   10
#define SCORE_T 1e-4f
#define CBUF   4096
#define BPI    16            /* front blocks per image */
#define NBLK1  (BATCH*BPI)   /* 128 */
#define HBINS  512           /* probs <= 1.0 -> key>>21 <= 508 */

typedef unsigned long long u64;

/* ---------------- scratch (static device globals; no allocation) -------- */
__device__ int      g_hist[BATCH][HBINS];  /* zeroed by k_mid for next replay */
__device__ int      g_ccount[BATCH];
__device__ u64      g_cbuf[BATCH][CBUF];
__device__ float    g_boxv[BATCH][KCAND][4];
__device__ int      g_prop[BATCH][KCAND];
__device__ short    g_member[BATCH][KCAND];
__device__ int      g_cnt[BATCH][NCLS];
__device__ int      g_cstart[BATCH][NCLS + 1];
__device__ unsigned g_validw[BATCH][32];
__device__ unsigned g_keepw[BATCH][NTH][32];   /* zeroed by k_mid */
__device__ unsigned char g_cmat_ovf[BATCH][1 << 20];

/* ------- device-wide sense barrier (128 blocks, all wave-1 resident) ----- */
__device__ unsigned g_ctr = 0;
__device__ unsigned g_gen = 0;
__device__ __forceinline__ void gridbar(unsigned nb)
{
    __syncthreads();
    if (threadIdx.x == 0) {
        __threadfence();
        unsigned gen = atomicAdd(&g_gen, 0u);
        if (atomicAdd(&g_ctr, 1u) == nb - 1u) {
            g_ctr = 0;
            __threadfence();
            atomicExch(&g_gen, gen + 1u);
        } else {
            while (atomicAdd(&g_gen, 0u) == gen) { __nanosleep(64); }
        }
        __threadfence();
    }
    __syncthreads();
}

/* ------ kernel 1: softmax -> keys(shared) + hist -> barrier -> compact --- */
__global__ void __launch_bounds__(256) k_front(const float* __restrict__ logits)
{
    int blk = blockIdx.x;
    int b  = blk / BPI;
    int sb = blk % BPI;
    int r0   = sb * 62 + (sb < 8 ? sb : 8);
    int rows = 62 + (sb < 8 ? 1 : 0);
    int nel  = rows * NCLS;

    __shared__ unsigned sh_keys[63 * NCLS];  /* 5040 */
    __shared__ int sh_hist[HBINS];
    __shared__ int sh_d1;

    int tid = threadIdx.x, lane = tid & 31, wid = tid >> 5;

    for (int i = tid; i < HBINS; i += 256) sh_hist[i] = 0;
    __syncthreads();

    for (int r = wid; r < rows; r += 8) {
        const float* p = logits + (size_t)(b * NPROP + r0 + r) * NLOG;
        float v0 = p[lane];
        float v1 = p[lane + 32];
        float v2 = (lane + 64 < NLOG) ? p[lane + 64] : -INFINITY;
        float m = fmaxf(fmaxf(v0, v1), v2);
        #pragma unroll
        for (int o = 16; o; o >>= 1) m = fmaxf(m, __shfl_xor_sync(0xffffffffu, m, o));
        float e0 = expf(v0 - m);
        float e1 = expf(v1 - m);
        float e2 = (lane + 64 < NLOG) ? expf(v2 - m) : 0.0f;
        float s = e0 + e1 + e2;
        #pragma unroll
        for (int o = 16; o; o >>= 1) s += __shfl_xor_sync(0xffffffffu, s, o);
        float p0 = e0 / s, p1 = e1 / s, p2 = e2 / s;
        unsigned k0 = (p0 > SCORE_T) ? __float_as_uint(p0) : 0u;
        unsigned k1 = (p1 > SCORE_T) ? __float_as_uint(p1) : 0u;
        unsigned k2 = (p2 > SCORE_T) ? __float_as_uint(p2) : 0u;
        sh_keys[r * NCLS + lane]      = k0;
        sh_keys[r * NCLS + lane + 32] = k1;
        if (k0) atomicAdd(&sh_hist[min(k0 >> 21, (unsigned)(HBINS - 1))], 1);
        if (k1) atomicAdd(&sh_hist[min(k1 >> 21, (unsigned)(HBINS - 1))], 1);
        if (lane + 64 < NCLS) {
            sh_keys[r * NCLS + lane + 64] = k2;
            if (k2) atomicAdd(&sh_hist[min(k2 >> 21, (unsigned)(HBINS - 1))], 1);
        }
    }
    __syncthreads();

    for (int i = tid; i < HBINS; i += 256) {
        int v = sh_hist[i];
        if (v) atomicAdd(&g_hist[b][i], v);
    }

    gridbar(NBLK1);

    /* pivot: highest bin where cumulative (from top) reaches KCAND */
    if (wid == 0) {
        int run = 0, found = 0;
        for (int g = 0; g < HBINS / 32; ++g) {
            int bin = HBINS - 1 - (g * 32 + lane);
            int c = g_hist[b][bin];
            int inc = c;
            #pragma unroll
            for (int o = 1; o < 32; o <<= 1) {
                int u = __shfl_up_sync(0xffffffffu, inc, o);
                if (lane >= o) inc += u;
            }
            int cum = run + inc;
            unsigned bal = __ballot_sync(0xffffffffu, cum >= KCAND);
            if (bal) {
                int fl = __ffs(bal) - 1;
                if (lane == fl) sh_d1 = bin;
                found = 1;
            }
            run += __shfl_sync(0xffffffffu, inc, 31);
            if (found) break;
        }
        if (!found && lane == 0) sh_d1 = 0;
    }
    __syncthreads();
    unsigned d1 = (unsigned)sh_d1;

    int iters = (nel + 255) / 256;
    for (int k = 0; k < iters; ++k) {
        int i = tid + k * 256;
        bool in = (i < nel);
        unsigned key = in ? sh_keys[i] : 0u;
        bool q = in && key && (min(key >> 21, (unsigned)(HBINS - 1)) >= d1);
        unsigned bal = __ballot_sync(0xffffffffu, q);
        if (bal) {
            int ldr = __ffs(bal) - 1;
            int pos = 0;
            if (lane == ldr) pos = atomicAdd(&g_ccount[b], __popc(bal));
            pos = __shfl_sync(0xffffffffu, pos, ldr);
            if (q) {
                int my = pos + __popc(bal & ((1u << lane) - 1));
                if (my < CBUF) {
                    unsigned idx = (unsigned)(r0 * NCLS + i);
                    g_cbuf[b][my] = ((u64)(key ^ 0xFFFFFFFFu) << 32) | idx;
                }
            }
        }
    }
}

/* ------ kernel 2: sort + finalize + class lists (one block per image) ---- */
__global__ void __launch_bounds__(1024) k_mid(const float* __restrict__ boxes,
                                              const int*   __restrict__ hw)
{
    int b = blockIdx.x;
    int tid = threadIdx.x, lane = tid & 31, wid = tid >> 5;

    __shared__ u64 sA[CBUF];                 /* 32KB sort buffer */
    __shared__ unsigned short h2[NCLS][32];
    __shared__ int sh_cnt[NCLS];
    __shared__ int sh_cstart[NCLS + 1];
    __shared__ int s_cnt;

    if (tid == 0) s_cnt = g_ccount[b];
    __syncthreads();
    int cnt = s_cnt;
    if (cnt > CBUF) cnt = CBUF;
    int M = 1024;
    while (M < cnt) M <<= 1;
    int E = M >> 10;

    for (int i = tid; i < M; i += 1024)
        sA[i] = (i < cnt) ? g_cbuf[b][i] : 0xFFFFFFFFFFFFFFFFULL;

    /* reset replay scratch */
    if (tid == 0) g_ccount[b] = 0;
    if (tid < HBINS) g_hist[b][tid] = 0;
    if (tid < NTH * 32) ((unsigned*)g_keepw[b])[tid] = 0;
    __syncthreads();

    /* hybrid bitonic sort ascending on (~val, idx); sub-sequences first */
    for (int k2 = 2; k2 < M; k2 <<= 1) {
        for (int j = k2 >> 1; j >= 32; j >>= 1) {
            for (int e = 0; e < E; ++e) {
                int i = tid + (e << 10);
                int ixj = i ^ j;
                if (ixj > i) {
                    u64 a = sA[i], c = sA[ixj];
                    bool up = ((i & k2) == 0);
                    if ((a > c) == up) { sA[i] = c; sA[ixj] = a; }
                }
            }
            __syncthreads();
        }
        int j0 = ((k2 >> 1) < 16) ? (k2 >> 1) : 16;
        for (int e = 0; e < E; ++e) {
            int i = tid + (e << 10);
            u64 a = sA[i];
            bool up = ((i & k2) == 0);
            #pragma unroll
            for (int j = 16; j > 0; j >>= 1) {
                if (j <= j0) {
                    u64 c = __shfl_xor_sync(0xffffffffu, a, j);
                    bool keepmin = (((i & j) == 0) == up);
                    bool amin = (a < c);
                    a = (keepmin == amin) ? a : c;
                }
            }
            sA[i] = a;
        }
        __syncthreads();
    }
    /* final merge k2 = M ascending; only the lowest KCAND matter */
    if (M > 1024) {
        for (int j = M >> 1; j >= 32; j >>= 1) {
            int lim = (2 * j > KCAND) ? 2 * j : KCAND;
            int El = lim >> 10;
            for (int e = 0; e < El; ++e) {
                int i = tid + (e << 10);
                int ixj = i ^ j;
                if (ixj > i) {
                    u64 a = sA[i], c = sA[ixj];
                    if (a > c) { sA[i] = c; sA[ixj] = a; }
                }
            }
            __syncthreads();
        }
        int i = tid;
        u64 a = sA[i];
        #pragma unroll
        for (int j = 16; j > 0; j >>= 1) {
            u64 c = __shfl_xor_sync(0xffffffffu, a, j);
            bool keepmin = ((i & j) == 0);
            bool amin = (a < c);
            a = (keepmin == amin) ? a : c;
        }
        sA[i] = a;
        __syncthreads();
    } else {
        /* M == 1024: single ascending merge over the full buffer */
        for (int j = 512; j >= 32; j >>= 1) {
            int i = tid;
            int ixj = i ^ j;
            if (ixj > i) {
                u64 a = sA[i], c = sA[ixj];
                if (a > c) { sA[i] = c; sA[ixj] = a; }
            }
            __syncthreads();
        }
        int i = tid;
        u64 a = sA[i];
        #pragma unroll
        for (int j = 16; j > 0; j >>= 1) {
            u64 c = __shfl_xor_sync(0xffffffffu, a, j);
            bool keepmin = ((i & j) == 0);
            bool amin = (a < c);
            a = (keepmin == amin) ? a : c;
        }
        sA[i] = a;
        __syncthreads();
    }

    u64 v = sA[tid];
    unsigned key = (unsigned)(v >> 32) ^ 0xFFFFFFFFu;
    unsigned idxu = (unsigned)(v & 0xFFFFFFFFu);
    int idx = (idxu < NFLAT) ? (int)idxu : 0;
    int cls  = idx % NCLS;
    int prop = idx / NCLS;

    float h = (float)hw[b * 2 + 0];
    float w = (float)hw[b * 2 + 1];
    const float* bp = boxes + ((size_t)(b * NPROP + prop) * NCLS + cls) * 4;
    float x1 = fminf(fmaxf(bp[0], 0.0f), w);
    float y1 = fminf(fmaxf(bp[1], 0.0f), h);
    float x2 = fminf(fmaxf(bp[2], 0.0f), w);
    float y2 = fminf(fmaxf(bp[3], 0.0f), h);
    float off = (float)cls * 4096.0f;
    x1 += off; y1 += off; x2 += off; y2 += off;

    g_boxv[b][tid][0] = x1; g_boxv[b][tid][1] = y1;
    g_boxv[b][tid][2] = x2; g_boxv[b][tid][3] = y2;
    g_prop[b][tid] = prop;

    unsigned vb = __ballot_sync(0xffffffffu, key != 0u);
    if (lane == 0) g_validw[b][wid] = vb;

    /* per-class member lists (stable in candidate order) */
    for (int i = tid; i < NCLS * 32; i += 1024) ((unsigned short*)h2)[i] = 0;
    __syncthreads();

    unsigned pm = __match_any_sync(0xffffffffu, cls);
    int leader = __ffs(pm) - 1;
    int intra  = __popc(pm & ((1u << lane) - 1));
    if (lane == leader) h2[cls][wid] = (unsigned short)__popc(pm);
    __syncthreads();

    if (tid < NCLS) {
        int acc = 0;
        #pragma unroll
        for (int w2 = 0; w2 < 32; ++w2) {
            int t = h2[tid][w2];
            h2[tid][w2] = (unsigned short)acc;
            acc += t;
        }
        sh_cnt[tid] = acc;
    }
    __syncthreads();
    if (tid == 0) {
        int acc = 0;
        for (int c = 0; c < NCLS; ++c) {
            sh_cstart[c] = acc;
            acc += sh_cnt[c];
        }
        sh_cstart[NCLS] = acc;
    }
    __syncthreads();

    int posc = sh_cstart[cls] + (int)h2[cls][wid] + intra;
    g_member[b][posc] = (short)tid;
    if (tid < NCLS) g_cnt[b][tid] = sh_cnt[tid];
    if (tid <= NCLS) g_cstart[b][tid] = sh_cstart[tid];
}

/* ------ kernel 3: per-class IOU + 10-threshold greedy chains ------------- */
__global__ void __launch_bounds__(128) k_nms2()
{
    int c = blockIdx.x;
    int b = blockIdx.y;
    int tid = threadIdx.x;

    int n = g_cnt[b][c];
    if (n == 0) return;
    int start = g_cstart[b][c];

    __shared__ short mem[KCAND];
    __shared__ float4 bx[256];               /* staged boxes if n<=256 */
    __shared__ unsigned char cm[128 * 128];
    __shared__ u64 sup_sh[NTH][16];
    __shared__ unsigned valid_sh[32];

    if (tid < 32) valid_sh[tid] = g_validw[b][tid];
    for (int i = tid; i < n; i += 128) mem[i] = g_member[b][start + i];
    __syncthreads();
    bool stage_bx = (n <= 256);
    if (stage_bx) {
        for (int i = tid; i < n; i += 128)
            bx[i] = ((const float4*)g_boxv[b])[(int)mem[i]];
    }
    bool use_sh = (n <= 128);
    unsigned char* Mp = use_sh ? cm : &g_cmat_ovf[b][start * 1024];
    __syncthreads();

    /* IOU -> per-pair threshold-count bytes */
    const float4* gb = (const float4*)g_boxv[b];
    int tot = n * n;
    for (int p = tid; p < tot; p += 128) {
        int q = p / n;
        int r = p - q * n;
        float4 bq = stage_bx ? bx[q] : gb[(int)mem[q]];
        float4 br = stage_bx ? bx[r] : gb[(int)mem[r]];
        float iw = fminf(bq.z, br.z) - fmaxf(bq.x, br.x);
        float ih = fminf(bq.w, br.w) - fmaxf(bq.y, br.y);
        iw = fmaxf(iw, 0.0f);
        ih = fmaxf(ih, 0.0f);
        float inter = iw * ih;
        float aq = (bq.z - bq.x) * (bq.w - bq.y);
        float ar = (br.z - br.x) * (br.w - br.y);
        float uni = aq + ar - inter;
        float iou = (uni > 0.0f) ? (inter / uni) : 0.0f;
        int cc = 0;
        cc += (iou > 0.001f); cc += (iou > 0.101f); cc += (iou > 0.201f);
        cc += (iou > 0.301f); cc += (iou > 0.401f); cc += (iou > 0.501f);
        cc += (iou > 0.601f); cc += (iou > 0.701f); cc += (iou > 0.801f);
        cc += (iou > 0.901f);
        Mp[p] = (unsigned char)cc;
    }
    if (tid < NTH * 16) ((u64*)sup_sh)[tid] = 0;
    __syncthreads();

    /* 10 serial greedy chains, one per thread */
    if (tid < NTH) {
        int t = tid;
        for (int r = 0; r < n; ++r) {
            if ((sup_sh[t][r >> 6] >> (r & 63)) & 1ULL) continue;
            int gi = (int)mem[r];
            if (!((valid_sh[gi >> 5] >> (gi & 31)) & 1u)) continue;
            atomicOr(&g_keepw[b][t][gi >> 5], 1u << (gi & 31));
            const unsigned char* row = Mp + r * n;
            u64 acc[16];
            int hi = (n + 63) >> 6;
            #pragma unroll 4
            for (int w2 = 0; w2 < hi; ++w2) acc[w2] = sup_sh[t][w2];
            for (int rr = r + 1; rr < n; ++rr)
                if ((int)row[rr] > t) acc[rr >> 6] |= 1ULL << (rr & 63);
            #pragma unroll 4
            for (int w2 = 0; w2 < hi; ++w2) sup_sh[t][w2] = acc[w2];
        }
    }
}

/* ------ kernel 4: threshold select (redundant) + top-6 + feature gather -- */
__global__ void __launch_bounds__(256) k_pick(const float* __restrict__ feats,
                                              float* __restrict__ out)
{
    int b = blockIdx.x;
    int s = blockIdx.y;          /* d-slice [s*256, (s+1)*256) */
    int tid = threadIdx.x;

    __shared__ unsigned keepw[NTH][32];
    __shared__ int cnt_t[NTH];
    __shared__ int selp[6];

    if (tid < NTH * 32) ((unsigned*)keepw)[tid] = ((const unsigned*)g_keepw[b])[tid];
    __syncthreads();

    if (tid < NTH) {
        int ssum = 0;
        #pragma unroll
        for (int w2 = 0; w2 < 32; ++w2) ssum += __popc(keepw[tid][w2]);
        cnt_t[tid] = ssum;
    }
    __syncthreads();

    if (tid == 0) {
        int tsel = NTH - 1;
        for (int q = 0; q < NTH; ++q)
            if (cnt_t[q] >= 6) { tsel = q; break; }
        int found = 0;
        for (int w2 = 0; w2 < 32 && found < 6; ++w2) {
            unsigned m = keepw[tsel][w2];
            while (m && found < 6) {
                int bpos = __ffs(m) - 1;
                m &= m - 1;
                selp[found++] = g_prop[b][w2 * 32 + bpos];
            }
        }
        if (found < 6) {
            for (int gi = 0; gi < KCAND && found < 6; ++gi)
                if (!((keepw[tsel][gi >> 5] >> (gi & 31)) & 1u))
                    selp[found++] = g_prop[b][gi];
        }
    }
    __syncthreads();

    int p0 = selp[0], p1 = selp[1], p2 = selp[2];
    int p3 = selp[3], p4 = selp[4], p5 = selp[5];
    const float* fb = feats + (size_t)b * NPROP * DFEAT;
    float* ob = out + (size_t)b * DFEAT * 6;
    int d = s * (DFEAT / 8) + tid;
    {
        float* o = ob + d * 6;
        o[0] = fb[(size_t)p0 * DFEAT + d];
        o[1] = fb[(size_t)p1 * DFEAT + d];
        o[2] = fb[(size_t)p2 * DFEAT + d];
        o[3] = fb[(size_t)p3 * DFEAT + d];
        o[4] = fb[(size_t)p4 * DFEAT + d];
        o[5] = fb[(size_t)p5 * DFEAT + d];
    }
}

/* ---------------- launch -------------------------------------------------- */
extern "C" void kernel_launch(void* const* d_in, const int* in_sizes, int n_in,
                              void* d_out, int out_size)
{
    (void)in_sizes; (void)n_in; (void)out_size;
    const float* logits = (const float*)d_in[0];
    const float* boxes  = (const float*)d_in[1];
    const float* feats  = (const float*)d_in[2];
    const int*   hw     = (const int*)  d_in[3];
    float* out = (float*)d_out;

    k_front<<<NBLK1, 256>>>(logits);
    k_mid<<<BATCH, 1024>>>(boxes, hw);
    k_nms2<<<dim3(NCLS, BATCH), 128>>>();
    k_pick<<<dim3(BATCH, 8), 256>>>(feats, out);
}